// round 1
// baseline (speedup 1.0000x reference)
#include <cuda_runtime.h>
#include <cstdint>

// Problem constants (fixed by the dataset: N=100000, E=1000000, H=8, C=10, HC=80)
#define NN   100000
#define EE   1000000
#define ET   (NN + EE)
#define HC   80
#define H    8
#define C    10

// ---------------- scratch (device globals; no allocation allowed) ------------
__device__ float    g_xl[(size_t)NN * HC];   // Wl x  (source transform)
__device__ float    g_xr[(size_t)NN * HC];   // Wr x  (target transform)
__device__ float    g_acc[(size_t)NN * HC];  // output accumulator / next-layer input
__device__ float    g_e[(size_t)ET * H];     // per-edge logits, then probs
__device__ unsigned g_emax[(size_t)NN * H];  // ordered-encoded segment max
__device__ float    g_den[(size_t)NN * H];   // softmax denominator

// ---------------- GEMM: Y[N,80] = X[N,DIN] @ W[DIN,80] ----------------------
// Block: 256 threads, 128 rows. X tile + W staged in smem. Each thread owns
// (1 row, 40 cols) with register accumulators.
template <int DIN>
__global__ __launch_bounds__(256) void gemm80(const float* __restrict__ X,
                                              const float* __restrict__ W,
                                              float* __restrict__ Y, int N) {
    extern __shared__ float sm[];
    float* xs = sm;                       // 128 x (DIN+1)  (padded vs bank conflicts)
    float* ws = sm + 128 * (DIN + 1);     // DIN x 80
    const int tid = threadIdx.x;
    const int row0 = blockIdx.x * 128;

    for (int i = tid; i < 128 * DIN; i += 256) {
        int r = i / DIN, k = i - r * DIN;
        int gr = row0 + r;
        xs[r * (DIN + 1) + k] = (gr < N) ? X[(size_t)gr * DIN + k] : 0.f;
    }
    for (int i = tid; i < DIN * HC; i += 256) ws[i] = W[i];
    __syncthreads();

    const int r = tid >> 1, ch = tid & 1;
    float acc[40];
#pragma unroll
    for (int j = 0; j < 40; j++) acc[j] = 0.f;
    const float* xp = xs + r * (DIN + 1);
    const float* wsp = ws + ch * 40;
#pragma unroll 4
    for (int k = 0; k < DIN; k++) {
        float xk = xp[k];
        const float4* w4 = (const float4*)(wsp + k * HC);
#pragma unroll
        for (int j = 0; j < 10; j++) {
            float4 w = w4[j];
            acc[4 * j + 0] += xk * w.x;
            acc[4 * j + 1] += xk * w.y;
            acc[4 * j + 2] += xk * w.z;
            acc[4 * j + 3] += xk * w.w;
        }
    }
    int grow = row0 + r;
    if (grow < N) {
        float4* o4 = (float4*)(Y + (size_t)grow * HC + ch * 40);
#pragma unroll
        for (int j = 0; j < 10; j++)
            o4[j] = make_float4(acc[4 * j], acc[4 * j + 1], acc[4 * j + 2], acc[4 * j + 3]);
    }
}

// ---------------- edge pass 1: logits + segment max --------------------------
__device__ __forceinline__ unsigned enc_f(float f) {
    unsigned u = __float_as_uint(f);
    return (u & 0x80000000u) ? ~u : (u | 0x80000000u);
}
__device__ __forceinline__ float dec_f(unsigned u) {
    return __uint_as_float((u & 0x80000000u) ? (u ^ 0x80000000u) : ~u);
}

__global__ void edge_logits(const int* __restrict__ ei,
                            const float* __restrict__ att, int E, int ET_) {
    int t = blockIdx.x * blockDim.x + threadIdx.x;
    if (t >= ET_ * H) return;
    int e = t >> 3, h = t & 7;
    int s, d;
    if (e < E) { s = ei[e]; d = ei[E + e]; } else { s = e - E; d = s; }

    const float2* xa = (const float2*)(g_xl + (size_t)s * HC + h * C);
    const float2* xb = (const float2*)(g_xr + (size_t)d * HC + h * C);
    const float2* at = (const float2*)(att + h * C);
    float acc = 0.f;
#pragma unroll
    for (int i = 0; i < 5; i++) {
        float2 a = __ldg(xa + i), b = __ldg(xb + i), w = __ldg(at + i);
        float v0 = a.x + b.x; v0 = v0 > 0.f ? v0 : 0.2f * v0;
        float v1 = a.y + b.y; v1 = v1 > 0.f ? v1 : 0.2f * v1;
        acc += w.x * v0 + w.y * v1;
    }
    g_e[(size_t)e * H + h] = acc;
    atomicMax(&g_emax[(size_t)d * H + h], enc_f(acc));
}

// ---------------- edge pass 2: exp + denominator -----------------------------
__global__ void edge_soft(const int* __restrict__ ei, int E, int ET_) {
    int t = blockIdx.x * blockDim.x + threadIdx.x;
    if (t >= ET_ * H) return;
    int e = t >> 3, h = t & 7;
    int d = (e < E) ? ei[E + e] : e - E;
    float m = dec_f(__ldg(&g_emax[(size_t)d * H + h]));
    float p = __expf(g_e[t] - m);
    g_e[t] = p;
    atomicAdd(&g_den[(size_t)d * H + h], p);
}

// ---------------- edge pass 3: alpha * xl[src] scatter-add -------------------
__global__ void edge_scatter(const int* __restrict__ ei, int E, int ET_) {
    int t = blockIdx.x * blockDim.x + threadIdx.x;
    if (t >= ET_ * H) return;
    int e = t >> 3, h = t & 7;
    int s, d;
    if (e < E) { s = ei[e]; d = ei[E + e]; } else { s = e - E; d = s; }
    float alpha = g_e[t] / __ldg(&g_den[(size_t)d * H + h]);
    const float* xs_ = g_xl + (size_t)s * HC + h * C;
    float* op = g_acc + (size_t)d * HC + h * C;
#pragma unroll
    for (int c = 0; c < C; c++) atomicAdd(op + c, alpha * __ldg(xs_ + c));
}

// ---------------- bias + ELU -------------------------------------------------
__global__ void finalize_k(const float* __restrict__ bias, float* __restrict__ out,
                           int n) {
    int t = blockIdx.x * blockDim.x + threadIdx.x;
    if (t >= n) return;
    int j = t % HC;
    float v = g_acc[t] + __ldg(bias + j);
    out[t] = v > 0.f ? v : expm1f(v);
}

// ---------------- launch -----------------------------------------------------
extern "C" void kernel_launch(void* const* d_in, const int* in_sizes, int n_in,
                              void* d_out, int out_size) {
    const float* x  = (const float*)d_in[0];
    const int*   ei = (const int*)d_in[1];
    const float* Wl[3]  = {(const float*)d_in[2], (const float*)d_in[6], (const float*)d_in[10]};
    const float* Wr[3]  = {(const float*)d_in[3], (const float*)d_in[7], (const float*)d_in[11]};
    const float* att[3] = {(const float*)d_in[4], (const float*)d_in[8], (const float*)d_in[12]};
    const float* bs[3]  = {(const float*)d_in[5], (const float*)d_in[9], (const float*)d_in[13]};

    const int N = NN, E = EE, ETn = ET;

    float *p_xl, *p_xr, *p_acc;
    unsigned* p_emax;
    float* p_den;
    cudaGetSymbolAddress((void**)&p_xl, g_xl);
    cudaGetSymbolAddress((void**)&p_xr, g_xr);
    cudaGetSymbolAddress((void**)&p_acc, g_acc);
    cudaGetSymbolAddress((void**)&p_emax, g_emax);
    cudaGetSymbolAddress((void**)&p_den, g_den);

    const int smem128 = (128 * 129 + 128 * HC) * sizeof(float);  // 107008 B
    const int smem80  = (128 * 81 + 80 * HC) * sizeof(float);    //  67072 B
    cudaFuncSetAttribute(gemm80<128>, cudaFuncAttributeMaxDynamicSharedMemorySize, smem128);
    cudaFuncSetAttribute(gemm80<80>,  cudaFuncAttributeMaxDynamicSharedMemorySize, smem80);

    const int gemmGrid = (N + 127) / 128;
    const int edgeThreads = ETn * H;
    const int edgeBlocks = (edgeThreads + 255) / 256;

    const float* xin = x;
    for (int l = 0; l < 3; l++) {
        const int din = (l == 0) ? 128 : HC;
        if (din == 128) {
            gemm80<128><<<gemmGrid, 256, smem128>>>(xin, Wl[l], p_xl, N);
            gemm80<128><<<gemmGrid, 256, smem128>>>(xin, Wr[l], p_xr, N);
        } else {
            gemm80<80><<<gemmGrid, 256, smem80>>>(xin, Wl[l], p_xl, N);
            gemm80<80><<<gemmGrid, 256, smem80>>>(xin, Wr[l], p_xr, N);
        }
        // safe to clear after the GEMMs of this layer consumed g_acc (stream order)
        cudaMemsetAsync(p_emax, 0, (size_t)N * H * sizeof(unsigned));
        cudaMemsetAsync(p_den, 0, (size_t)N * H * sizeof(float));
        cudaMemsetAsync(p_acc, 0, (size_t)N * HC * sizeof(float));

        edge_logits<<<edgeBlocks, 256>>>(ei, att[l], E, ETn);
        edge_soft<<<edgeBlocks, 256>>>(ei, E, ETn);
        edge_scatter<<<edgeBlocks, 256>>>(ei, E, ETn);

        float* xout = (l == 2) ? (float*)d_out : p_acc;
        int n = N * HC;
        finalize_k<<<(n + 255) / 256, 256>>>(bs[l], xout, n);
        xin = p_acc;
    }
}

// round 2
// speedup vs baseline: 1.6586x; 1.6586x over previous
#include <cuda_runtime.h>
#include <cstdint>

// Problem constants: N=100000, E=1000000, H=8, C=10, HC=80
#define NN   100000
#define EE   1000000
#define ET   (NN + EE)
#define HC   80
#define H    8
#define C    10
#define CP   12              // padded C so each head slice is 16B aligned
#define HCP  (H * CP)        // 96

// ---------------- scratch (device globals; no allocation allowed) ------------
__device__ float    g_xl[(size_t)NN * HC];    // Wl x  (source transform)
__device__ float    g_xr[(size_t)NN * HC];    // Wr x  (target transform)
__device__ float    g_acc[(size_t)NN * HCP];  // padded output accumulator
__device__ float    g_h[(size_t)NN * HC];     // compacted activations (next input)
__device__ float    g_e[(size_t)ET * H];      // per-edge logits, then probs
__device__ unsigned g_emax[(size_t)NN * H];   // ordered-encoded segment max
__device__ float    g_den[(size_t)NN * H];    // softmax denominator

// ---------------- GEMM: Y[N,80] = X[N,DIN] @ W[DIN,80] ----------------------
// 256 threads = 16 row-tiles x 16 col-tiles; thread owns 8 rows x 5 cols.
// X staged k-major (xs[k][row]) so row fragment = 2x LDS.128.
template <int DIN, int KC>
__global__ __launch_bounds__(256) void gemm_k(const float* __restrict__ X,
                                              const float* __restrict__ W,
                                              float* __restrict__ Y, int N) {
    __shared__ float xs[KC][132];   // k-major, padded
    __shared__ float ws[KC][80];
    const int tid = threadIdx.x;
    const int row0 = blockIdx.x * 128;
    const int tx = tid & 15, ty = tid >> 4;
    const int r0 = ty * 8, c0 = tx * 5;

    float acc[8][5];
#pragma unroll
    for (int i = 0; i < 8; i++)
#pragma unroll
        for (int j = 0; j < 5; j++) acc[i][j] = 0.f;

    for (int k0 = 0; k0 < DIN; k0 += KC) {
        __syncthreads();
        // X chunk: transpose-store. i = kq*128 + r  (conflict-free smem stores)
        for (int i = tid; i < 128 * (KC / 4); i += 256) {
            int kq = i >> 7, r = i & 127;
            int gr = row0 + r;
            float4 v = make_float4(0.f, 0.f, 0.f, 0.f);
            if (gr < N) v = *(const float4*)(X + (size_t)gr * DIN + k0 + kq * 4);
            xs[kq * 4 + 0][r] = v.x;
            xs[kq * 4 + 1][r] = v.y;
            xs[kq * 4 + 2][r] = v.z;
            xs[kq * 4 + 3][r] = v.w;
        }
        // W chunk: contiguous (coalesced load, conflict-free store)
        for (int i = tid; i < KC * 80; i += 256)
            (&ws[0][0])[i] = W[(size_t)k0 * 80 + i];
        __syncthreads();

#pragma unroll 8
        for (int k = 0; k < KC; k++) {
            float4 a = *(const float4*)&xs[k][r0];
            float4 b = *(const float4*)&xs[k][r0 + 4];
            float xr_[8] = {a.x, a.y, a.z, a.w, b.x, b.y, b.z, b.w};
            float wf[5];
#pragma unroll
            for (int j = 0; j < 5; j++) wf[j] = ws[k][c0 + j];
#pragma unroll
            for (int i = 0; i < 8; i++)
#pragma unroll
                for (int j = 0; j < 5; j++) acc[i][j] += xr_[i] * wf[j];
        }
    }

#pragma unroll
    for (int i = 0; i < 8; i++) {
        int grow = row0 + r0 + i;
        if (grow < N) {
            float* yp = Y + (size_t)grow * 80 + c0;
#pragma unroll
            for (int j = 0; j < 5; j++) yp[j] = acc[i][j];
        }
    }
}

// ---------------- ordered-float encoding for atomicMax -----------------------
__device__ __forceinline__ unsigned enc_f(float f) {
    unsigned u = __float_as_uint(f);
    return (u & 0x80000000u) ? ~u : (u | 0x80000000u);
}
__device__ __forceinline__ float dec_f(unsigned u) {
    return __uint_as_float((u & 0x80000000u) ? (u ^ 0x80000000u) : ~u);
}

// ---------------- edge pass 1: logits + segment max --------------------------
__global__ void edge_logits(const int* __restrict__ ei,
                            const float* __restrict__ att, int E, int ET_) {
    int t = blockIdx.x * blockDim.x + threadIdx.x;
    if (t >= ET_ * H) return;
    int e = t >> 3, h = t & 7;
    int s, d;
    if (e < E) { s = ei[e]; d = ei[E + e]; } else { s = e - E; d = s; }

    const float2* xa = (const float2*)(g_xl + (size_t)s * HC + h * C);
    const float2* xb = (const float2*)(g_xr + (size_t)d * HC + h * C);
    const float2* at = (const float2*)(att + h * C);
    float acc = 0.f;
#pragma unroll
    for (int i = 0; i < 5; i++) {
        float2 a = __ldg(xa + i), b = __ldg(xb + i), w = __ldg(at + i);
        float v0 = a.x + b.x; v0 = v0 > 0.f ? v0 : 0.2f * v0;
        float v1 = a.y + b.y; v1 = v1 > 0.f ? v1 : 0.2f * v1;
        acc += w.x * v0 + w.y * v1;
    }
    g_e[(size_t)e * H + h] = acc;
    atomicMax(&g_emax[(size_t)d * H + h], enc_f(acc));
}

// ---------------- edge pass 2: exp + denominator -----------------------------
__global__ void edge_soft(const int* __restrict__ ei, int E, int ET_) {
    int t = blockIdx.x * blockDim.x + threadIdx.x;
    if (t >= ET_ * H) return;
    int e = t >> 3, h = t & 7;
    int d = (e < E) ? ei[E + e] : e - E;
    float m = dec_f(__ldg(&g_emax[(size_t)d * H + h]));
    float p = __expf(g_e[t] - m);
    g_e[t] = p;
    atomicAdd(&g_den[(size_t)d * H + h], p);
}

// ---------------- edge pass 3: alpha * xl[src] vector scatter-add ------------
__global__ void edge_scatter(const int* __restrict__ ei, int E, int ET_) {
    int t = blockIdx.x * blockDim.x + threadIdx.x;
    if (t >= ET_ * H) return;
    int e = t >> 3, h = t & 7;
    int s, d;
    if (e < E) { s = ei[e]; d = ei[E + e]; } else { s = e - E; d = s; }
    float alpha = g_e[t] / __ldg(&g_den[(size_t)d * H + h]);

    const float2* xp = (const float2*)(g_xl + (size_t)s * HC + h * C);
    float v[10];
#pragma unroll
    for (int i = 0; i < 5; i++) {
        float2 a = __ldg(xp + i);
        v[2 * i] = alpha * a.x;
        v[2 * i + 1] = alpha * a.y;
    }
    float* op = g_acc + (size_t)d * HCP + h * CP;   // 16B aligned (48B * h)
    asm volatile("red.global.add.v4.f32 [%0], {%1,%2,%3,%4};"
                 :: "l"(op), "f"(v[0]), "f"(v[1]), "f"(v[2]), "f"(v[3]) : "memory");
    asm volatile("red.global.add.v4.f32 [%0], {%1,%2,%3,%4};"
                 :: "l"(op + 4), "f"(v[4]), "f"(v[5]), "f"(v[6]), "f"(v[7]) : "memory");
    asm volatile("red.global.add.v2.f32 [%0], {%1,%2};"
                 :: "l"(op + 8), "f"(v[8]), "f"(v[9]) : "memory");
}

// ---------------- bias + ELU (compact padded acc -> dense output) ------------
__global__ void finalize_k(const float* __restrict__ bias, float* __restrict__ out,
                           int n) {
    int t = blockIdx.x * blockDim.x + threadIdx.x;
    if (t >= n) return;
    int node = t / HC, j = t - node * HC;
    int h = j / C, c = j - h * C;
    float v = g_acc[(size_t)node * HCP + h * CP + c] + __ldg(bias + j);
    out[t] = v > 0.f ? v : expm1f(v);
}

// ---------------- launch -----------------------------------------------------
extern "C" void kernel_launch(void* const* d_in, const int* in_sizes, int n_in,
                              void* d_out, int out_size) {
    const float* x  = (const float*)d_in[0];
    const int*   ei = (const int*)d_in[1];
    const float* Wl[3]  = {(const float*)d_in[2], (const float*)d_in[6], (const float*)d_in[10]};
    const float* Wr[3]  = {(const float*)d_in[3], (const float*)d_in[7], (const float*)d_in[11]};
    const float* att[3] = {(const float*)d_in[4], (const float*)d_in[8], (const float*)d_in[12]};
    const float* bs[3]  = {(const float*)d_in[5], (const float*)d_in[9], (const float*)d_in[13]};

    const int N = NN, E = EE, ETn = ET;

    float *p_xl, *p_xr, *p_acc, *p_h;
    unsigned* p_emax;
    float* p_den;
    cudaGetSymbolAddress((void**)&p_xl, g_xl);
    cudaGetSymbolAddress((void**)&p_xr, g_xr);
    cudaGetSymbolAddress((void**)&p_acc, g_acc);
    cudaGetSymbolAddress((void**)&p_h, g_h);
    cudaGetSymbolAddress((void**)&p_emax, g_emax);
    cudaGetSymbolAddress((void**)&p_den, g_den);

    const int gemmGrid = (N + 127) / 128;
    const int edgeThreads = ETn * H;
    const int edgeBlocks = (edgeThreads + 255) / 256;

    const float* xin = x;
    for (int l = 0; l < 3; l++) {
        if (l == 0) {
            gemm_k<128, 32><<<gemmGrid, 256>>>(xin, Wl[l], p_xl, N);
            gemm_k<128, 32><<<gemmGrid, 256>>>(xin, Wr[l], p_xr, N);
        } else {
            gemm_k<80, 16><<<gemmGrid, 256>>>(xin, Wl[l], p_xl, N);
            gemm_k<80, 16><<<gemmGrid, 256>>>(xin, Wr[l], p_xr, N);
        }
        cudaMemsetAsync(p_emax, 0, (size_t)N * H * sizeof(unsigned));
        cudaMemsetAsync(p_den, 0, (size_t)N * H * sizeof(float));
        cudaMemsetAsync(p_acc, 0, (size_t)N * HCP * sizeof(float));

        edge_logits<<<edgeBlocks, 256>>>(ei, att[l], E, ETn);
        edge_soft<<<edgeBlocks, 256>>>(ei, E, ETn);
        edge_scatter<<<edgeBlocks, 256>>>(ei, E, ETn);

        float* xout = (l == 2) ? (float*)d_out : p_h;
        int n = N * HC;
        finalize_k<<<(n + 255) / 256, 256>>>(bs[l], xout, n);
        xin = p_h;
    }
}

// round 3
// speedup vs baseline: 2.9851x; 1.7998x over previous
#include <cuda_runtime.h>
#include <cstdint>

// Problem constants: N=100000, E=1000000, H=8, C=10, HC=80
#define NN   100000
#define EE   1000000
#define HC   80
#define H    8
#define C    10

// ---------------- scratch (device globals) -----------------------------------
__device__ float g_xl[(size_t)NN * HC];   // Wl x  (source transform)
__device__ float g_xr[(size_t)NN * HC];   // Wr x  (target transform)
__device__ float g_h[(size_t)NN * HC];    // layer activations (next input)
__device__ int   g_deg[NN];
__device__ int   g_rowptr[NN + 1];
__device__ int   g_cursor[NN];
__device__ int   g_csr[EE];               // src indices grouped by dst

// ---------------- GEMM: Y[N,80] = X[N,DIN] @ W[DIN,80] ----------------------
template <int DIN, int KC>
__global__ __launch_bounds__(256) void gemm_k(const float* __restrict__ X,
                                              const float* __restrict__ W,
                                              float* __restrict__ Y, int N) {
    __shared__ float xs[KC][132];   // k-major, padded
    __shared__ float ws[KC][80];
    const int tid = threadIdx.x;
    const int row0 = blockIdx.x * 128;
    const int tx = tid & 15, ty = tid >> 4;
    const int r0 = ty * 8, c0 = tx * 5;

    float acc[8][5];
#pragma unroll
    for (int i = 0; i < 8; i++)
#pragma unroll
        for (int j = 0; j < 5; j++) acc[i][j] = 0.f;

    for (int k0 = 0; k0 < DIN; k0 += KC) {
        __syncthreads();
        for (int i = tid; i < 128 * (KC / 4); i += 256) {
            int kq = i >> 7, r = i & 127;
            int gr = row0 + r;
            float4 v = make_float4(0.f, 0.f, 0.f, 0.f);
            if (gr < N) v = *(const float4*)(X + (size_t)gr * DIN + k0 + kq * 4);
            xs[kq * 4 + 0][r] = v.x;
            xs[kq * 4 + 1][r] = v.y;
            xs[kq * 4 + 2][r] = v.z;
            xs[kq * 4 + 3][r] = v.w;
        }
        for (int i = tid; i < KC * 80; i += 256)
            (&ws[0][0])[i] = W[(size_t)k0 * 80 + i];
        __syncthreads();

#pragma unroll 8
        for (int k = 0; k < KC; k++) {
            float4 a = *(const float4*)&xs[k][r0];
            float4 b = *(const float4*)&xs[k][r0 + 4];
            float xf[8] = {a.x, a.y, a.z, a.w, b.x, b.y, b.z, b.w};
            float wf[5];
#pragma unroll
            for (int j = 0; j < 5; j++) wf[j] = ws[k][c0 + j];
#pragma unroll
            for (int i = 0; i < 8; i++)
#pragma unroll
                for (int j = 0; j < 5; j++) acc[i][j] += xf[i] * wf[j];
        }
    }

#pragma unroll
    for (int i = 0; i < 8; i++) {
        int grow = row0 + r0 + i;
        if (grow < N) {
            float* yp = Y + (size_t)grow * 80 + c0;
#pragma unroll
            for (int j = 0; j < 5; j++) yp[j] = acc[i][j];
        }
    }
}

// ---------------- CSR build --------------------------------------------------
__global__ void hist_k(const int* __restrict__ ei) {
    int t = blockIdx.x * blockDim.x + threadIdx.x;
    if (t < EE) atomicAdd(&g_deg[ei[EE + t]], 1);
}

// single block, 1024 threads: exclusive scan of g_deg -> g_rowptr / g_cursor
__global__ __launch_bounds__(1024) void scan_k() {
    __shared__ int warpsum[32];
    __shared__ int s_carry;
    const int tid = threadIdx.x;
    const int lane = tid & 31, wid = tid >> 5;
    if (tid == 0) s_carry = 0;
    __syncthreads();
    for (int base = 0; base < NN; base += 1024) {
        int i = base + tid;
        int v = (i < NN) ? g_deg[i] : 0;
        int incl = v;
#pragma unroll
        for (int o = 1; o < 32; o <<= 1) {
            int n = __shfl_up_sync(0xffffffffu, incl, o);
            if (lane >= o) incl += n;
        }
        if (lane == 31) warpsum[wid] = incl;
        __syncthreads();
        if (tid < 32) {
            int w = warpsum[tid];
            int wi = w;
#pragma unroll
            for (int o = 1; o < 32; o <<= 1) {
                int n = __shfl_up_sync(0xffffffffu, wi, o);
                if (tid >= o) wi += n;
            }
            warpsum[tid] = wi - w;  // exclusive warp offset
        }
        __syncthreads();
        int excl = s_carry + warpsum[wid] + incl - v;
        if (i < NN) { g_rowptr[i] = excl; g_cursor[i] = excl; }
        __syncthreads();
        if (tid == 1023) s_carry = excl + v;   // chunk total carried forward
        __syncthreads();
    }
    if (tid == 0) g_rowptr[NN] = s_carry;      // == EE
}

__global__ void fill_k(const int* __restrict__ ei) {
    int t = blockIdx.x * blockDim.x + threadIdx.x;
    if (t >= EE) return;
    int s = ei[t], d = ei[EE + t];
    int p = atomicAdd(&g_cursor[d], 1);
    g_csr[p] = s;
}

// ---------------- fused attention aggregate (online softmax) -----------------
// thread per (dst, head). Self-loop is the initializer. Bias+ELU fused.
__global__ __launch_bounds__(256) void agg_k(const float* __restrict__ att,
                                             const float* __restrict__ bias,
                                             float* __restrict__ out) {
    int t = blockIdx.x * blockDim.x + threadIdx.x;
    if (t >= NN * H) return;
    int d = t >> 3, h = t & 7;

    float xr_[10], at[10];
    {
        const float2* xrp = (const float2*)(g_xr + (size_t)d * HC + h * C);
        const float2* atp = (const float2*)(att + h * C);
#pragma unroll
        for (int i = 0; i < 5; i++) {
            float2 a = __ldg(xrp + i);
            xr_[2 * i] = a.x; xr_[2 * i + 1] = a.y;
            float2 w = __ldg(atp + i);
            at[2 * i] = w.x; at[2 * i + 1] = w.y;
        }
    }

    // self loop init
    float acc[10];
    float m, ssum = 1.f;
    {
        const float2* xsp = (const float2*)(g_xl + (size_t)d * HC + h * C);
        float e = 0.f;
#pragma unroll
        for (int i = 0; i < 5; i++) {
            float2 a = __ldg(xsp + i);
            acc[2 * i] = a.x; acc[2 * i + 1] = a.y;
            float v0 = a.x + xr_[2 * i];     v0 = v0 > 0.f ? v0 : 0.2f * v0;
            float v1 = a.y + xr_[2 * i + 1]; v1 = v1 > 0.f ? v1 : 0.2f * v1;
            e += at[2 * i] * v0 + at[2 * i + 1] * v1;
        }
        m = e;
    }

    const int beg = __ldg(&g_rowptr[d]);
    const int end = __ldg(&g_rowptr[d + 1]);
    for (int j = beg; j < end; j++) {
        int s = __ldg(&g_csr[j]);
        const float2* xsp = (const float2*)(g_xl + (size_t)s * HC + h * C);
        float xs_[10];
        float e = 0.f;
#pragma unroll
        for (int i = 0; i < 5; i++) {
            float2 a = __ldg(xsp + i);
            xs_[2 * i] = a.x; xs_[2 * i + 1] = a.y;
            float v0 = a.x + xr_[2 * i];     v0 = v0 > 0.f ? v0 : 0.2f * v0;
            float v1 = a.y + xr_[2 * i + 1]; v1 = v1 > 0.f ? v1 : 0.2f * v1;
            e += at[2 * i] * v0 + at[2 * i + 1] * v1;
        }
        if (e <= m) {
            float p = __expf(e - m);
            ssum += p;
#pragma unroll
            for (int c = 0; c < 10; c++) acc[c] += p * xs_[c];
        } else {
            float r = __expf(m - e);
            ssum = ssum * r + 1.f;
#pragma unroll
            for (int c = 0; c < 10; c++) acc[c] = acc[c] * r + xs_[c];
            m = e;
        }
    }

    float inv = 1.f / ssum;
    float2* op = (float2*)(out + (size_t)d * HC + h * C);
#pragma unroll
    for (int i = 0; i < 5; i++) {
        float b0 = __ldg(bias + h * C + 2 * i);
        float b1 = __ldg(bias + h * C + 2 * i + 1);
        float v0 = acc[2 * i] * inv + b0;
        float v1 = acc[2 * i + 1] * inv + b1;
        v0 = v0 > 0.f ? v0 : expm1f(v0);
        v1 = v1 > 0.f ? v1 : expm1f(v1);
        op[i] = make_float2(v0, v1);
    }
}

// ---------------- launch -----------------------------------------------------
extern "C" void kernel_launch(void* const* d_in, const int* in_sizes, int n_in,
                              void* d_out, int out_size) {
    const float* x  = (const float*)d_in[0];
    const int*   ei = (const int*)d_in[1];
    const float* Wl[3]  = {(const float*)d_in[2], (const float*)d_in[6], (const float*)d_in[10]};
    const float* Wr[3]  = {(const float*)d_in[3], (const float*)d_in[7], (const float*)d_in[11]};
    const float* att[3] = {(const float*)d_in[4], (const float*)d_in[8], (const float*)d_in[12]};
    const float* bs[3]  = {(const float*)d_in[5], (const float*)d_in[9], (const float*)d_in[13]};

    const int N = NN;

    float *p_xl, *p_xr, *p_h;
    int* p_deg;
    cudaGetSymbolAddress((void**)&p_xl, g_xl);
    cudaGetSymbolAddress((void**)&p_xr, g_xr);
    cudaGetSymbolAddress((void**)&p_h, g_h);
    cudaGetSymbolAddress((void**)&p_deg, g_deg);

    // ---- CSR build (once; reused by all 3 layers) ----
    cudaMemsetAsync(p_deg, 0, (size_t)NN * sizeof(int));
    hist_k<<<(EE + 255) / 256, 256>>>(ei);
    scan_k<<<1, 1024>>>();
    fill_k<<<(EE + 255) / 256, 256>>>(ei);

    const int gemmGrid = (N + 127) / 128;
    const int aggBlocks = (NN * H + 255) / 256;

    const float* xin = x;
    for (int l = 0; l < 3; l++) {
        if (l == 0) {
            gemm_k<128, 32><<<gemmGrid, 256>>>(xin, Wl[l], p_xl, N);
            gemm_k<128, 32><<<gemmGrid, 256>>>(xin, Wr[l], p_xr, N);
        } else {
            gemm_k<80, 16><<<gemmGrid, 256>>>(xin, Wl[l], p_xl, N);
            gemm_k<80, 16><<<gemmGrid, 256>>>(xin, Wr[l], p_xr, N);
        }
        float* xout = (l == 2) ? (float*)d_out : p_h;
        agg_k<<<aggBlocks, 256>>>(att[l], bs[l], xout);
        xin = p_h;
    }
}

// round 4
// speedup vs baseline: 3.1022x; 1.0392x over previous
#include <cuda_runtime.h>
#include <cstdint>

// Problem constants: N=100000, E=1000000, H=8, C=10, HC=80
#define NN   100000
#define EE   1000000
#define HC   80
#define H    8
#define C    10

typedef unsigned long long u64;

// ---------------- packed f32x2 helpers (Blackwell FFMA2) ---------------------
__device__ __forceinline__ u64 fma2(u64 a, u64 b, u64 c) {
    u64 d;
    asm("fma.rn.f32x2 %0, %1, %2, %3;" : "=l"(d) : "l"(a), "l"(b), "l"(c));
    return d;
}
__device__ __forceinline__ u64 pack2(float v) {
    u64 d;
    asm("mov.b64 %0, {%1, %2};" : "=l"(d) : "f"(v), "f"(v));
    return d;
}
__device__ __forceinline__ float2 unpack2(u64 v) {
    float lo, hi;
    asm("mov.b64 {%0, %1}, %2;" : "=f"(lo), "=f"(hi) : "l"(v));
    return make_float2(lo, hi);
}

// ---------------- scratch (device globals) -----------------------------------
__device__ float g_xl[(size_t)NN * HC];   // Wl x  (source transform)
__device__ float g_xr[(size_t)NN * HC];   // Wr x  (target transform)
__device__ float g_h[(size_t)NN * HC];    // layer activations (next input)
__device__ int   g_deg[NN];
__device__ int   g_rowptr[NN + 1];
__device__ int   g_cursor[NN];
__device__ int   g_csr[EE];               // src indices grouped by dst

// ---------------- fused GEMM: Yl = X@Wl, Yr = X@Wr  (f32x2 math) -------------
// 256 threads, 128 rows/block, full K in smem. Thread: 8 rows x (5+5) cols.
// acc[j][i] packs rows (r0+2i, r0+2i+1) for col group j (0-4 Wl, 5-9 Wr).
template <int DIN>
__global__ __launch_bounds__(256) void gemm_fused(
    const float* __restrict__ X, const float* __restrict__ Wl,
    const float* __restrict__ Wr, float* __restrict__ Yl,
    float* __restrict__ Yr, int N) {
    extern __shared__ float sm[];
    float* xs = sm;                    // [DIN][132] k-major (padded)
    float* wl = sm + DIN * 132;        // [DIN][80]
    float* wr = wl + DIN * 80;

    const int tid = threadIdx.x;
    const int row0 = blockIdx.x * 128;

    // X: coalesced float4 reads along rows, transpose-store to k-major
    for (int i = tid; i < 128 * (DIN / 4); i += 256) {
        int r = i / (DIN / 4), kq = i % (DIN / 4);
        int gr = row0 + r;
        float4 v = make_float4(0.f, 0.f, 0.f, 0.f);
        if (gr < N) v = *(const float4*)(X + (size_t)gr * DIN + kq * 4);
        xs[(kq * 4 + 0) * 132 + r] = v.x;
        xs[(kq * 4 + 1) * 132 + r] = v.y;
        xs[(kq * 4 + 2) * 132 + r] = v.z;
        xs[(kq * 4 + 3) * 132 + r] = v.w;
    }
    // W: contiguous float4 copies
    for (int i = tid; i < DIN * 20; i += 256) {
        ((float4*)wl)[i] = ((const float4*)Wl)[i];
        ((float4*)wr)[i] = ((const float4*)Wr)[i];
    }
    __syncthreads();

    const int tx = tid & 15, ty = tid >> 4;
    const int r0 = ty * 8, c0 = tx * 5;

    u64 acc[10][4];
#pragma unroll
    for (int j = 0; j < 10; j++)
#pragma unroll
        for (int i = 0; i < 4; i++) acc[j][i] = 0ull;

#pragma unroll 2
    for (int k = 0; k < DIN; k++) {
        ulonglong2 xa = *(const ulonglong2*)&xs[k * 132 + r0];
        ulonglong2 xb = *(const ulonglong2*)&xs[k * 132 + r0 + 4];
        u64 xf[4] = {xa.x, xa.y, xb.x, xb.y};
        u64 wp[10];
#pragma unroll
        for (int j = 0; j < 5; j++) wp[j] = pack2(wl[k * 80 + c0 + j]);
#pragma unroll
        for (int j = 0; j < 5; j++) wp[5 + j] = pack2(wr[k * 80 + c0 + j]);
#pragma unroll
        for (int j = 0; j < 10; j++)
#pragma unroll
            for (int i = 0; i < 4; i++)
                acc[j][i] = fma2(wp[j], xf[i], acc[j][i]);
    }

#pragma unroll
    for (int i = 0; i < 4; i++) {
        int ga = row0 + r0 + 2 * i;
        int gb = ga + 1;
        float va[10], vb[10];
#pragma unroll
        for (int j = 0; j < 10; j++) {
            float2 v = unpack2(acc[j][i]);
            va[j] = v.x; vb[j] = v.y;
        }
        if (ga < N) {
            float* yl = Yl + (size_t)ga * 80 + c0;
            float* yr = Yr + (size_t)ga * 80 + c0;
#pragma unroll
            for (int j = 0; j < 5; j++) { yl[j] = va[j]; yr[j] = va[5 + j]; }
        }
        if (gb < N) {
            float* yl = Yl + (size_t)gb * 80 + c0;
            float* yr = Yr + (size_t)gb * 80 + c0;
#pragma unroll
            for (int j = 0; j < 5; j++) { yl[j] = vb[j]; yr[j] = vb[5 + j]; }
        }
    }
}

// ---------------- CSR build --------------------------------------------------
__global__ void hist_k(const int* __restrict__ ei) {
    int t = blockIdx.x * blockDim.x + threadIdx.x;
    if (t < EE) atomicAdd(&g_deg[ei[EE + t]], 1);
}

__global__ __launch_bounds__(1024) void scan_k() {
    __shared__ int warpsum[32];
    __shared__ int s_carry;
    const int tid = threadIdx.x;
    const int lane = tid & 31, wid = tid >> 5;
    if (tid == 0) s_carry = 0;
    __syncthreads();
    for (int base = 0; base < NN; base += 1024) {
        int i = base + tid;
        int v = (i < NN) ? g_deg[i] : 0;
        int incl = v;
#pragma unroll
        for (int o = 1; o < 32; o <<= 1) {
            int n = __shfl_up_sync(0xffffffffu, incl, o);
            if (lane >= o) incl += n;
        }
        if (lane == 31) warpsum[wid] = incl;
        __syncthreads();
        if (tid < 32) {
            int w = warpsum[tid];
            int wi = w;
#pragma unroll
            for (int o = 1; o < 32; o <<= 1) {
                int n = __shfl_up_sync(0xffffffffu, wi, o);
                if (tid >= o) wi += n;
            }
            warpsum[tid] = wi - w;  // exclusive warp offset
        }
        __syncthreads();
        int excl = s_carry + warpsum[wid] + incl - v;
        if (i < NN) { g_rowptr[i] = excl; g_cursor[i] = excl; }
        __syncthreads();
        if (tid == 1023) s_carry = excl + v;
        __syncthreads();
    }
    if (tid == 0) g_rowptr[NN] = s_carry;
}

__global__ void fill_k(const int* __restrict__ ei) {
    int t = blockIdx.x * blockDim.x + threadIdx.x;
    if (t >= EE) return;
    int s = ei[t], d = ei[EE + t];
    int p = atomicAdd(&g_cursor[d], 1);
    g_csr[p] = s;
}

// ---------------- fused attention aggregate (online softmax) -----------------
__global__ __launch_bounds__(256) void agg_k(const float* __restrict__ att,
                                             const float* __restrict__ bias,
                                             float* __restrict__ out) {
    int t = blockIdx.x * blockDim.x + threadIdx.x;
    if (t >= NN * H) return;
    int d = t >> 3, h = t & 7;

    float xr_[10], at[10];
    {
        const float2* xrp = (const float2*)(g_xr + (size_t)d * HC + h * C);
        const float2* atp = (const float2*)(att + h * C);
#pragma unroll
        for (int i = 0; i < 5; i++) {
            float2 a = __ldg(xrp + i);
            xr_[2 * i] = a.x; xr_[2 * i + 1] = a.y;
            float2 w = __ldg(atp + i);
            at[2 * i] = w.x; at[2 * i + 1] = w.y;
        }
    }

    float acc[10];
    float m, ssum = 1.f;
    {
        const float2* xsp = (const float2*)(g_xl + (size_t)d * HC + h * C);
        float e = 0.f;
#pragma unroll
        for (int i = 0; i < 5; i++) {
            float2 a = __ldg(xsp + i);
            acc[2 * i] = a.x; acc[2 * i + 1] = a.y;
            float v0 = a.x + xr_[2 * i];     v0 = v0 > 0.f ? v0 : 0.2f * v0;
            float v1 = a.y + xr_[2 * i + 1]; v1 = v1 > 0.f ? v1 : 0.2f * v1;
            e += at[2 * i] * v0 + at[2 * i + 1] * v1;
        }
        m = e;
    }

    const int beg = __ldg(&g_rowptr[d]);
    const int end = __ldg(&g_rowptr[d + 1]);
    for (int j = beg; j < end; j++) {
        int s = __ldg(&g_csr[j]);
        const float2* xsp = (const float2*)(g_xl + (size_t)s * HC + h * C);
        float xs_[10];
        float e = 0.f;
#pragma unroll
        for (int i = 0; i < 5; i++) {
            float2 a = __ldg(xsp + i);
            xs_[2 * i] = a.x; xs_[2 * i + 1] = a.y;
            float v0 = a.x + xr_[2 * i];     v0 = v0 > 0.f ? v0 : 0.2f * v0;
            float v1 = a.y + xr_[2 * i + 1]; v1 = v1 > 0.f ? v1 : 0.2f * v1;
            e += at[2 * i] * v0 + at[2 * i + 1] * v1;
        }
        if (e <= m) {
            float p = __expf(e - m);
            ssum += p;
#pragma unroll
            for (int c = 0; c < 10; c++) acc[c] += p * xs_[c];
        } else {
            float r = __expf(m - e);
            ssum = ssum * r + 1.f;
#pragma unroll
            for (int c = 0; c < 10; c++) acc[c] = acc[c] * r + xs_[c];
            m = e;
        }
    }

    float inv = 1.f / ssum;
    float2* op = (float2*)(out + (size_t)d * HC + h * C);
#pragma unroll
    for (int i = 0; i < 5; i++) {
        float b0 = __ldg(bias + h * C + 2 * i);
        float b1 = __ldg(bias + h * C + 2 * i + 1);
        float v0 = acc[2 * i] * inv + b0;
        float v1 = acc[2 * i + 1] * inv + b1;
        v0 = v0 > 0.f ? v0 : expm1f(v0);
        v1 = v1 > 0.f ? v1 : expm1f(v1);
        op[i] = make_float2(v0, v1);
    }
}

// ---------------- launch -----------------------------------------------------
extern "C" void kernel_launch(void* const* d_in, const int* in_sizes, int n_in,
                              void* d_out, int out_size) {
    const float* x  = (const float*)d_in[0];
    const int*   ei = (const int*)d_in[1];
    const float* Wl[3]  = {(const float*)d_in[2], (const float*)d_in[6], (const float*)d_in[10]};
    const float* Wr[3]  = {(const float*)d_in[3], (const float*)d_in[7], (const float*)d_in[11]};
    const float* att[3] = {(const float*)d_in[4], (const float*)d_in[8], (const float*)d_in[12]};
    const float* bs[3]  = {(const float*)d_in[5], (const float*)d_in[9], (const float*)d_in[13]};

    const int N = NN;

    float *p_xl, *p_xr, *p_h;
    int* p_deg;
    cudaGetSymbolAddress((void**)&p_xl, g_xl);
    cudaGetSymbolAddress((void**)&p_xr, g_xr);
    cudaGetSymbolAddress((void**)&p_h, g_h);
    cudaGetSymbolAddress((void**)&p_deg, g_deg);

    // ---- CSR build (once; reused by all 3 layers) ----
    cudaMemsetAsync(p_deg, 0, (size_t)NN * sizeof(int));
    hist_k<<<(EE + 255) / 256, 256>>>(ei);
    scan_k<<<1, 1024>>>();
    fill_k<<<(EE + 255) / 256, 256>>>(ei);

    const int smem128 = (128 * 132 + 2 * 128 * 80) * sizeof(float);  // 149504
    const int smem80  = (80 * 132 + 2 * 80 * 80) * sizeof(float);    //  93440
    cudaFuncSetAttribute(gemm_fused<128>, cudaFuncAttributeMaxDynamicSharedMemorySize, smem128);
    cudaFuncSetAttribute(gemm_fused<80>,  cudaFuncAttributeMaxDynamicSharedMemorySize, smem80);

    const int gemmGrid = (N + 127) / 128;
    const int aggBlocks = (NN * H + 255) / 256;

    const float* xin = x;
    for (int l = 0; l < 3; l++) {
        if (l == 0)
            gemm_fused<128><<<gemmGrid, 256, smem128>>>(xin, Wl[l], Wr[l], p_xl, p_xr, N);
        else
            gemm_fused<80><<<gemmGrid, 256, smem80>>>(xin, Wl[l], Wr[l], p_xl, p_xr, N);
        float* xout = (l == 2) ? (float*)d_out : p_h;
        agg_k<<<aggBlocks, 256>>>(att[l], bs[l], xout);
        xin = p_h;
    }
}

// round 5
// speedup vs baseline: 3.3213x; 1.0706x over previous
#include <cuda_runtime.h>
#include <cstdint>

// Problem constants: N=100000, E=1000000, H=8, C=10, HC=80
#define NN   100000
#define EE   1000000
#define HC   80
#define H    8
#define C    10

typedef unsigned long long u64;

// ---------------- packed f32x2 helpers (Blackwell FFMA2) ---------------------
__device__ __forceinline__ u64 fma2(u64 a, u64 b, u64 c) {
    u64 d;
    asm("fma.rn.f32x2 %0, %1, %2, %3;" : "=l"(d) : "l"(a), "l"(b), "l"(c));
    return d;
}
__device__ __forceinline__ u64 pack2(float v) {
    u64 d;
    asm("mov.b64 %0, {%1, %2};" : "=l"(d) : "f"(v), "f"(v));
    return d;
}
__device__ __forceinline__ float2 unpack2(u64 v) {
    float lo, hi;
    asm("mov.b64 {%0, %1}, %2;" : "=f"(lo), "=f"(hi) : "l"(v));
    return make_float2(lo, hi);
}

// ---------------- scratch (device globals) -----------------------------------
__device__ float g_xl[(size_t)NN * HC];   // Wl x  (source transform)
__device__ float g_xr[(size_t)NN * HC];   // Wr x  (target transform)
__device__ float g_h[(size_t)NN * HC];    // layer activations (next input)
__device__ int   g_deg[NN];
__device__ int   g_rowptr[NN + 1];
__device__ int   g_cursor[NN];
__device__ int   g_csr[EE];               // src indices grouped by dst

// ---------------- fused GEMM: Yl = X@Wl, Yr = X@Wr  (f32x2, chunked) ---------
// 256 threads, 128 rows/block, KC-chunked. Thread: 8 rows x (5 Wl + 5 Wr).
// acc[j][i] packs rows (r0+2i, r0+2i+1); j: 0-4 Wl cols, 5-9 Wr cols.
template <int DIN, int KC>
__global__ __launch_bounds__(256, 2) void gemm2(
    const float* __restrict__ X, const float* __restrict__ Wl,
    const float* __restrict__ Wr, float* __restrict__ Yl,
    float* __restrict__ Yr, int N) {
    __shared__ float xs[KC][132];   // k-major, padded
    __shared__ float wb[KC][160];   // [k][0:80)=Wl, [k][80:160)=Wr

    const int tid = threadIdx.x;
    const int row0 = blockIdx.x * 128;
    const int tx = tid & 15, ty = tid >> 4;
    const int r0 = ty * 8, c0 = tx * 5;

    u64 acc[10][4];
#pragma unroll
    for (int j = 0; j < 10; j++)
#pragma unroll
        for (int i = 0; i < 4; i++) acc[j][i] = 0ull;

    for (int k0 = 0; k0 < DIN; k0 += KC) {
        __syncthreads();
        // X chunk: i = kq*128 + r -> conflict-free smem stores
        for (int i = tid; i < 128 * (KC / 4); i += 256) {
            int kq = i >> 7, r = i & 127;
            int gr = row0 + r;
            float4 v = make_float4(0.f, 0.f, 0.f, 0.f);
            if (gr < N) v = *(const float4*)(X + (size_t)gr * DIN + k0 + kq * 4);
            xs[kq * 4 + 0][r] = v.x;
            xs[kq * 4 + 1][r] = v.y;
            xs[kq * 4 + 2][r] = v.z;
            xs[kq * 4 + 3][r] = v.w;
        }
        // W chunks (coalesced reads; stores conflict-light)
        for (int i = tid; i < KC * 80; i += 256) {
            int k = i / 80, c = i - k * 80;
            wb[k][c] = Wl[(size_t)(k0 + k) * 80 + c];
            wb[k][80 + c] = Wr[(size_t)(k0 + k) * 80 + c];
        }
        __syncthreads();

#pragma unroll 4
        for (int k = 0; k < KC; k++) {
            ulonglong2 xa = *(const ulonglong2*)&xs[k][r0];
            ulonglong2 xb = *(const ulonglong2*)&xs[k][r0 + 4];
            u64 xf[4] = {xa.x, xa.y, xb.x, xb.y};
            u64 wp[10];
#pragma unroll
            for (int j = 0; j < 5; j++) wp[j] = pack2(wb[k][c0 + j]);
#pragma unroll
            for (int j = 0; j < 5; j++) wp[5 + j] = pack2(wb[k][80 + c0 + j]);
#pragma unroll
            for (int j = 0; j < 10; j++)
#pragma unroll
                for (int i = 0; i < 4; i++)
                    acc[j][i] = fma2(wp[j], xf[i], acc[j][i]);
        }
    }

#pragma unroll
    for (int i = 0; i < 4; i++) {
        int ga = row0 + r0 + 2 * i;
        int gb = ga + 1;
        float va[10], vb[10];
#pragma unroll
        for (int j = 0; j < 10; j++) {
            float2 v = unpack2(acc[j][i]);
            va[j] = v.x; vb[j] = v.y;
        }
        if (ga < N) {
            float* yl = Yl + (size_t)ga * 80 + c0;
            float* yr = Yr + (size_t)ga * 80 + c0;
#pragma unroll
            for (int j = 0; j < 5; j++) { yl[j] = va[j]; yr[j] = va[5 + j]; }
        }
        if (gb < N) {
            float* yl = Yl + (size_t)gb * 80 + c0;
            float* yr = Yr + (size_t)gb * 80 + c0;
#pragma unroll
            for (int j = 0; j < 5; j++) { yl[j] = vb[j]; yr[j] = vb[5 + j]; }
        }
    }
}

// ---------------- CSR build --------------------------------------------------
__global__ void hist_k(const int* __restrict__ ei) {
    int t = blockIdx.x * blockDim.x + threadIdx.x;
    if (t < EE) atomicAdd(&g_deg[ei[EE + t]], 1);
}

__global__ __launch_bounds__(1024) void scan_k() {
    __shared__ int warpsum[32];
    __shared__ int s_carry;
    const int tid = threadIdx.x;
    const int lane = tid & 31, wid = tid >> 5;
    if (tid == 0) s_carry = 0;
    __syncthreads();
    for (int base = 0; base < NN; base += 1024) {
        int i = base + tid;
        int v = (i < NN) ? g_deg[i] : 0;
        int incl = v;
#pragma unroll
        for (int o = 1; o < 32; o <<= 1) {
            int n = __shfl_up_sync(0xffffffffu, incl, o);
            if (lane >= o) incl += n;
        }
        if (lane == 31) warpsum[wid] = incl;
        __syncthreads();
        if (tid < 32) {
            int w = warpsum[tid];
            int wi = w;
#pragma unroll
            for (int o = 1; o < 32; o <<= 1) {
                int n = __shfl_up_sync(0xffffffffu, wi, o);
                if (tid >= o) wi += n;
            }
            warpsum[tid] = wi - w;
        }
        __syncthreads();
        int excl = s_carry + warpsum[wid] + incl - v;
        if (i < NN) { g_rowptr[i] = excl; g_cursor[i] = excl; }
        __syncthreads();
        if (tid == 1023) s_carry = excl + v;
        __syncthreads();
    }
    if (tid == 0) g_rowptr[NN] = s_carry;
}

__global__ void fill_k(const int* __restrict__ ei) {
    int t = blockIdx.x * blockDim.x + threadIdx.x;
    if (t >= EE) return;
    int s = ei[t], d = ei[EE + t];
    int p = atomicAdd(&g_cursor[d], 1);
    g_csr[p] = s;
}

// ---------------- fused attention aggregate (online softmax) -----------------
__global__ __launch_bounds__(256) void agg_k(const float* __restrict__ att,
                                             const float* __restrict__ bias,
                                             float* __restrict__ out) {
    int t = blockIdx.x * blockDim.x + threadIdx.x;
    if (t >= NN * H) return;
    int d = t >> 3, h = t & 7;

    float xr_[10], at[10];
    {
        const float2* xrp = (const float2*)(g_xr + (size_t)d * HC + h * C);
        const float2* atp = (const float2*)(att + h * C);
#pragma unroll
        for (int i = 0; i < 5; i++) {
            float2 a = __ldg(xrp + i);
            xr_[2 * i] = a.x; xr_[2 * i + 1] = a.y;
            float2 w = __ldg(atp + i);
            at[2 * i] = w.x; at[2 * i + 1] = w.y;
        }
    }

    float acc[10];
    float m, ssum = 1.f;
    {
        const float2* xsp = (const float2*)(g_xl + (size_t)d * HC + h * C);
        float e = 0.f;
#pragma unroll
        for (int i = 0; i < 5; i++) {
            float2 a = __ldg(xsp + i);
            acc[2 * i] = a.x; acc[2 * i + 1] = a.y;
            float v0 = a.x + xr_[2 * i];     v0 = v0 > 0.f ? v0 : 0.2f * v0;
            float v1 = a.y + xr_[2 * i + 1]; v1 = v1 > 0.f ? v1 : 0.2f * v1;
            e += at[2 * i] * v0 + at[2 * i + 1] * v1;
        }
        m = e;
    }

    const int beg = __ldg(&g_rowptr[d]);
    const int end = __ldg(&g_rowptr[d + 1]);
    for (int j = beg; j < end; j++) {
        int s = __ldg(&g_csr[j]);
        const float2* xsp = (const float2*)(g_xl + (size_t)s * HC + h * C);
        float xs_[10];
        float e = 0.f;
#pragma unroll
        for (int i = 0; i < 5; i++) {
            float2 a = __ldg(xsp + i);
            xs_[2 * i] = a.x; xs_[2 * i + 1] = a.y;
            float v0 = a.x + xr_[2 * i];     v0 = v0 > 0.f ? v0 : 0.2f * v0;
            float v1 = a.y + xr_[2 * i + 1]; v1 = v1 > 0.f ? v1 : 0.2f * v1;
            e += at[2 * i] * v0 + at[2 * i + 1] * v1;
        }
        if (e <= m) {
            float p = __expf(e - m);
            ssum += p;
#pragma unroll
            for (int c = 0; c < 10; c++) acc[c] += p * xs_[c];
        } else {
            float r = __expf(m - e);
            ssum = ssum * r + 1.f;
#pragma unroll
            for (int c = 0; c < 10; c++) acc[c] = acc[c] * r + xs_[c];
            m = e;
        }
    }

    float inv = 1.f / ssum;
    float2* op = (float2*)(out + (size_t)d * HC + h * C);
#pragma unroll
    for (int i = 0; i < 5; i++) {
        float b0 = __ldg(bias + h * C + 2 * i);
        float b1 = __ldg(bias + h * C + 2 * i + 1);
        float v0 = acc[2 * i] * inv + b0;
        float v1 = acc[2 * i + 1] * inv + b1;
        v0 = v0 > 0.f ? v0 : expm1f(v0);
        v1 = v1 > 0.f ? v1 : expm1f(v1);
        op[i] = make_float2(v0, v1);
    }
}

// ---------------- launch -----------------------------------------------------
extern "C" void kernel_launch(void* const* d_in, const int* in_sizes, int n_in,
                              void* d_out, int out_size) {
    const float* x  = (const float*)d_in[0];
    const int*   ei = (const int*)d_in[1];
    const float* Wl[3]  = {(const float*)d_in[2], (const float*)d_in[6], (const float*)d_in[10]};
    const float* Wr[3]  = {(const float*)d_in[3], (const float*)d_in[7], (const float*)d_in[11]};
    const float* att[3] = {(const float*)d_in[4], (const float*)d_in[8], (const float*)d_in[12]};
    const float* bs[3]  = {(const float*)d_in[5], (const float*)d_in[9], (const float*)d_in[13]};

    const int N = NN;

    float *p_xl, *p_xr, *p_h;
    int* p_deg;
    cudaGetSymbolAddress((void**)&p_xl, g_xl);
    cudaGetSymbolAddress((void**)&p_xr, g_xr);
    cudaGetSymbolAddress((void**)&p_h, g_h);
    cudaGetSymbolAddress((void**)&p_deg, g_deg);

    // ---- CSR build (once; reused by all 3 layers) ----
    cudaMemsetAsync(p_deg, 0, (size_t)NN * sizeof(int));
    hist_k<<<(EE + 255) / 256, 256>>>(ei);
    scan_k<<<1, 1024>>>();
    fill_k<<<(EE + 255) / 256, 256>>>(ei);

    const int gemmGrid = (N + 127) / 128;
    const int aggBlocks = (NN * H + 255) / 256;

    const float* xin = x;
    for (int l = 0; l < 3; l++) {
        if (l == 0)
            gemm2<128, 32><<<gemmGrid, 256>>>(xin, Wl[l], Wr[l], p_xl, p_xr, N);
        else
            gemm2<80, 40><<<gemmGrid, 256>>>(xin, Wl[l], Wr[l], p_xl, p_xr, N);
        float* xout = (l == 2) ? (float*)d_out : p_h;
        agg_k<<<aggBlocks, 256>>>(att[l], bs[l], xout);
        xin = p_h;
    }
}